// round 13
// baseline (speedup 1.0000x reference)
#include <cuda_runtime.h>
#include <cstdint>

// Dims: Nt=64, Nr=64, Mt=32, Mr=32, G^2=4096, num_sc=32, B=64, R=8, N_r_RF=4
#define G2 4096
typedef unsigned long long u64;

// ---- device globals (no allocation allowed) ----
__device__ float4 g_W4[2048];   // [d*32+m] = (w.x,w.x,w.y,-w.y)  conj form
__device__ float4 g_F4[2048];   // [c*32+a] = (f.x,f.x,-f.y,f.y)  mul form
__device__ float2 g_S [(size_t)2048 * 4096];        // S[c*32+bp][g], 64 MB
__device__ float2 g_G1[(size_t)2048 * 2048];        // G1[b*32+m][c*32+s], 32 MB
__device__ unsigned g_ctr1, g_ctr2;                 // work-stealing counters

// ---- f32x2 packed helpers ----
__device__ __forceinline__ u64 ffma2(u64 a, u64 b, u64 c) {
    u64 d; asm("fma.rn.f32x2 %0,%1,%2,%3;" : "=l"(d) : "l"(a), "l"(b), "l"(c)); return d;
}
__device__ __forceinline__ u64 fadd2(u64 a, u64 b) {
    u64 d; asm("add.rn.f32x2 %0,%1,%2;" : "=l"(d) : "l"(a), "l"(b)); return d;
}
__device__ __forceinline__ u64 swap2(u64 v) {
    uint2 t; asm("mov.b64 {%0,%1},%2;" : "=r"(t.x), "=r"(t.y) : "l"(v));
    u64 r;  asm("mov.b64 %0,{%1,%2};" : "=l"(r) : "r"(t.y), "r"(t.x));
    return r;
}
__device__ __forceinline__ uint32_t saddr(const void* p) {
    return (uint32_t)__cvta_generic_to_shared(p);
}
__device__ __forceinline__ void lds_v2(u64& a, u64& b, uint32_t addr) {
    asm volatile("ld.shared.v2.b64 {%0,%1},[%2];" : "=l"(a), "=l"(b) : "r"(addr));
}
__device__ __forceinline__ void ldg_v2(u64& a, u64& b, const void* p) {
    asm("ld.global.nc.v2.b64 {%0,%1},[%2];" : "=l"(a), "=l"(b) : "l"(p));
}
__device__ __forceinline__ void ldg_v2_c(u64& a, u64& b, const void* p) {
    asm volatile("ld.global.v2.b64 {%0,%1},[%2];" : "=l"(a), "=l"(b) : "l"(p));
}
__device__ __forceinline__ void stg_v2(void* p, u64 a, u64 b) {
    asm volatile("st.global.v2.b64 [%0],{%1,%2};" :: "l"(p), "l"(a), "l"(b));
}
__device__ __forceinline__ void ldg4(u64* k, const float2* p) {
    ldg_v2(k[0], k[1], p);
    ldg_v2(k[2], k[3], p + 2);
}
__device__ __forceinline__ void pref_l2(const void* p) {
    asm volatile("prefetch.global.L2 [%0];" :: "l"(p));
}

// ---- setup: tables + counter reset (runs first every graph replay) ----
__global__ void setup_kernel(const float* __restrict__ kW, const float* __restrict__ kF) {
    int i = blockIdx.x * blockDim.x + threadIdx.x;
    if (i == 0) { g_ctr1 = 0u; g_ctr2 = 0u; }
    if (i < 2048) {
        float s, c;
        sincosf(kW[i], &s, &c);
        c *= 0.125f; s *= 0.125f;
        g_W4[i] = make_float4(c, c, s, -s);     // conj form
        sincosf(kF[i], &s, &c);
        c *= 0.125f; s *= 0.125f;
        g_F4[i] = make_float4(c, c, -s, s);     // mul form
    }
}

// =====================================================================
// R12-proven core (byte-identical): 8 rows x 2 cols, K=64,
// depth-2 register prefetch + L2 prefetch(+6), guard-peeled.
// =====================================================================
#define C8X2_BODY(DD)                                                        \
    {                                                                        \
        const u64 ks0 = swap2(ka0), ks1 = swap2(ka1);                        \
        _Pragma("unroll")                                                    \
        for (int i = 0; i < 8; ++i) {                                        \
            u64 wxx, wyn;                                                    \
            lds_v2(wxx, wyn, taddr_ + (uint32_t)(DD) * 512 + i * 16);        \
            acc0[i] = ffma2(wyn, ks0, ffma2(wxx, ka0, acc0[i]));             \
            acc1[i] = ffma2(wyn, ks1, ffma2(wxx, ka1, acc1[i]));             \
        }                                                                    \
        ka0 = kb0; ka1 = kb1; kb0 = kn0; kb1 = kn1;                          \
    }

#define CORE8x2(PTR, STRIDE, TADDR)                                          \
    u64 acc0[8], acc1[8];                                                    \
    _Pragma("unroll")                                                        \
    for (int i = 0; i < 8; ++i) { acc0[i] = 0ull; acc1[i] = 0ull; }          \
    const uint32_t taddr_ = (TADDR);                                         \
    u64 ka0, ka1, kb0, kb1;                                                  \
    ldg_v2(ka0, ka1, (PTR));                                                 \
    ldg_v2(kb0, kb1, (PTR) + (STRIDE));                                      \
    _Pragma("unroll")                                                        \
    for (int pd = 2; pd < 6; ++pd) pref_l2((PTR) + (size_t)pd * (STRIDE));   \
    _Pragma("unroll 2")                                                      \
    for (int dd = 0; dd < 56; ++dd) {                                        \
        u64 kn0, kn1;                                                        \
        ldg_v2(kn0, kn1, (PTR) + (size_t)(dd + 2) * (STRIDE));               \
        pref_l2((PTR) + (size_t)(dd + 6) * (STRIDE));                        \
        C8X2_BODY(dd)                                                        \
    }                                                                        \
    _Pragma("unroll 2")                                                      \
    for (int dd = 56; dd < 62; ++dd) {                                       \
        u64 kn0, kn1;                                                        \
        ldg_v2(kn0, kn1, (PTR) + (size_t)(dd + 2) * (STRIDE));               \
        C8X2_BODY(dd)                                                        \
    }                                                                        \
    _Pragma("unroll")                                                        \
    for (int dd = 62; dd < 64; ++dd) {                                       \
        u64 kn0 = 0ull, kn1 = 0ull;                                          \
        C8X2_BODY(dd)                                                        \
    }

#define LOAD_TABLE(DST, SRC)                                                 \
    _Pragma("unroll")                                                        \
    for (int i = 0; i < 8; ++i) DST[threadIdx.x + 256 * i] = SRC[threadIdx.x + 256 * i]; \
    __syncthreads();

#define NEXT_ITEM(CTR, SHVAR)                                                \
    __syncthreads();                                                         \
    if (t == 0) SHVAR = atomicAdd(&CTR, 1u);                                 \
    __syncthreads();

// =====================================================================
// k1 persistent, 3584 items, stripe: item%7==6 -> y2n (512, inits Y);
// else oid = item - item/7:  [0,2048) sA, [2048,3072) y1.
// =====================================================================
__global__ void __launch_bounds__(256, 3) k1_kernel(const float2* __restrict__ K,
                                                    const float2* __restrict__ H,
                                                    const float2* __restrict__ noise,
                                                    float2* __restrict__ Y) {
    __shared__ float4 Tab[2048];
    __shared__ unsigned s_item;
    const int t = threadIdx.x;
    LOAD_TABLE(Tab, g_W4)
    const int gp = t & 63, rg = t >> 6;
    const uint32_t taddr = saddr(Tab) + (uint32_t)(rg * 8) * 16;

    for (;;) {
        NEXT_ITEM(g_ctr1, s_item)
        const unsigned bid = s_item;
        if (bid >= 3584u) break;

        if (bid % 7u == 6u) {
            // ---------------- y2n (coeffs via broadcast LDG) ----------------
            const int blk = bid / 7u;             // 0..511
            const int b = blk >> 3, r = blk & 7;
            const int x0 = t * 4;
            const float2* np = noise + (size_t)(b * 8 + r) * 65536 + x0;
            const float4* wp = g_W4 + r * 4;      // + n*32 + j

            u64 acc[4][4];
#pragma unroll
            for (int j = 0; j < 4; ++j)
#pragma unroll
                for (int q = 0; q < 4; ++q) acc[j][q] = 0ull;

#define Y2N_BODY(N)                                                          \
            {                                                                \
                const u64 w0 = swap2(v[0]), w1 = swap2(v[1]),                \
                          w2 = swap2(v[2]), w3 = swap2(v[3]);                \
                _Pragma("unroll")                                            \
                for (int j = 0; j < 4; ++j) {                                \
                    u64 wxx, wyn;                                            \
                    ldg_v2(wxx, wyn, wp + (N) * 32 + j);                     \
                    acc[j][0] = ffma2(wyn, w0, ffma2(wxx, v[0], acc[j][0])); \
                    acc[j][1] = ffma2(wyn, w1, ffma2(wxx, v[1], acc[j][1])); \
                    acc[j][2] = ffma2(wyn, w2, ffma2(wxx, v[2], acc[j][2])); \
                    acc[j][3] = ffma2(wyn, w3, ffma2(wxx, v[3], acc[j][3])); \
                }                                                            \
            }

#pragma unroll 4
            for (int n = 0; n < 56; ++n) {
                u64 v[4];
                ldg4(v, np + (size_t)n * 1024);
                pref_l2(np + (size_t)(n + 8) * 1024);
                Y2N_BODY(n)
            }
#pragma unroll 4
            for (int n = 56; n < 64; ++n) {
                u64 v[4];
                ldg4(v, np + (size_t)n * 1024);
                Y2N_BODY(n)
            }

            const int a = x0 >> 5, s = x0 & 31;
#pragma unroll
            for (int j = 0; j < 4; ++j) {
                float2* yp = Y + (size_t)(b * 1024 + a * 32 + r * 4 + j) * 32 + s;
                stg_v2(yp,     acc[j][0], acc[j][1]);     // WRITE (init)
                stg_v2(yp + 2, acc[j][2], acc[j][3]);
            }
            continue;
        }

        const int oid = (int)(bid - bid / 7u);    // 0..3071
        if (oid < 2048) {
            // ---------------- sA ----------------
            const int c = oid >> 5, gt = oid & 31;
            const int g = gt * 128 + gp * 2;
            const float2* Kp = K + (size_t)(c * 64) * G2 + g;

            CORE8x2(Kp, G2, taddr)

#pragma unroll
            for (int i = 0; i < 8; ++i) {
                float2* Sp = g_S + (size_t)(c * 32 + rg * 8 + i) * G2 + g;
                stg_v2(Sp, acc0[i], acc1[i]);
            }
        } else {
            // ---------------- y1 ----------------
            const int blk = oid - 2048;
            const int b = blk >> 4, cst = blk & 15;
            const int cs = cst * 128 + gp * 2;
            const float2* Hp = H + (size_t)b * 131072 + cs;    // + d*2048

            CORE8x2(Hp, 2048, taddr)

#pragma unroll
            for (int i = 0; i < 8; ++i) {
                float2* Gp = g_G1 + (size_t)(b * 32 + rg * 8 + i) * 2048 + cs;
                stg_v2(Gp, acc0[i], acc1[i]);
            }
        }
    }
}

// =====================================================================
// k2 persistent, 1536 items, stripe: item%3==2 -> y2s (512, RMW);
// else pid = item - item/3 in [0,1024) -> phiB.
// =====================================================================
__global__ void __launch_bounds__(256, 3) k2_kernel(float2* __restrict__ Phi,
                                                    float2* __restrict__ Y) {
    __shared__ float4 Ft[2048];
    __shared__ unsigned s_item;
    const int t = threadIdx.x;
    LOAD_TABLE(Ft, g_F4)

    for (;;) {
        NEXT_ITEM(g_ctr2, s_item)
        const unsigned bid = s_item;
        if (bid >= 1536u) break;

        if (bid % 3u == 2u) {
            // ---------------- y2s (RMW) ----------------
            const int blk = bid / 3u;             // 0..511
            const int bm = blk * 4 + (t >> 6);
            const int b = bm >> 5, m = bm & 31;
            const int sp = t & 15, ag = (t >> 4) & 3;
            const int s = sp * 2;

            const float2* Gp = g_G1 + (size_t)bm * 2048 + s;   // + c*32
            const uint32_t faddr = saddr(Ft) + (uint32_t)(ag * 8) * 16;

            CORE8x2(Gp, 32, faddr)

#pragma unroll
            for (int i = 0; i < 8; ++i) {
                float2* yp = Y + (size_t)(b * 1024 + (ag * 8 + i) * 32 + m) * 32 + s;
                u64 y0, y1;
                ldg_v2_c(y0, y1, yp);
                stg_v2(yp, fadd2(y0, acc0[i]), fadd2(y1, acc1[i]));
            }
        } else {
            // ---------------- phiB ----------------
            const int pid = (int)(bid - bid / 3u);    // 0..1023
            const int gp = t & 63, ag = t >> 6;
            const int bp = pid >> 5, gt = pid & 31;
            const int g = gt * 128 + gp * 2;

            const float2* Sp = g_S + (size_t)bp * G2 + g;      // + c*32*G2
            const uint32_t faddr = saddr(Ft) + (uint32_t)(ag * 8) * 16;

            CORE8x2(Sp, (size_t)32 * G2, faddr)

#pragma unroll
            for (int i = 0; i < 8; ++i) {
                float2* Pp = Phi + (size_t)((ag * 8 + i) * 32 + bp) * G2 + g;
                stg_v2(Pp, acc0[i], acc1[i]);
            }
        }
    }
}

extern "C" void kernel_launch(void* const* d_in, const int* in_sizes, int n_in,
                              void* d_out, int out_size) {
    const float2* H     = (const float2*)d_in[0];  // (64,64,64,32,2) f32
    const float2* noise = (const float2*)d_in[1];  // (64,8,64,1024,2) f32
    const float*  kW    = (const float*)d_in[2];   // (64,32)
    const float*  kF    = (const float*)d_in[3];   // (64,32)
    const float2* K     = (const float2*)d_in[4];  // (4096,4096,2)

    float2* Phi = (float2*)d_out;                   // 1024*4096 complex
    float2* Y   = Phi + (size_t)1024 * 4096;        // 64*1024*32 complex

    setup_kernel<<<8, 256>>>(kW, kF);
    k1_kernel<<<456, 256>>>(K, H, noise, Y);        // persistent, work-stealing
    k2_kernel<<<456, 256>>>(Phi, Y);                // persistent, work-stealing
}

// round 14
// speedup vs baseline: 1.0495x; 1.0495x over previous
#include <cuda_runtime.h>
#include <cstdint>

// Dims: Nt=64, Nr=64, Mt=32, Mr=32, G^2=4096, num_sc=32, B=64, R=8, N_r_RF=4
#define G2 4096
typedef unsigned long long u64;

// ---- device globals (no allocation allowed) ----
__device__ float4 g_W4[2048];   // [d*32+m] = (w.x,w.x,w.y,-w.y)  conj form
__device__ float4 g_F4[2048];   // [c*32+a] = (f.x,f.x,-f.y,f.y)  mul form
__device__ float2 g_S [(size_t)2048 * 4096];        // S[c*32+bp][g], 64 MB
__device__ float2 g_G1[(size_t)2048 * 2048];        // G1[b*32+m][c*32+s], 32 MB

// ---- f32x2 packed helpers ----
__device__ __forceinline__ u64 ffma2(u64 a, u64 b, u64 c) {
    u64 d; asm("fma.rn.f32x2 %0,%1,%2,%3;" : "=l"(d) : "l"(a), "l"(b), "l"(c)); return d;
}
__device__ __forceinline__ u64 fadd2(u64 a, u64 b) {
    u64 d; asm("add.rn.f32x2 %0,%1,%2;" : "=l"(d) : "l"(a), "l"(b)); return d;
}
__device__ __forceinline__ u64 swap2(u64 v) {
    uint2 t; asm("mov.b64 {%0,%1},%2;" : "=r"(t.x), "=r"(t.y) : "l"(v));
    u64 r;  asm("mov.b64 %0,{%1,%2};" : "=l"(r) : "r"(t.y), "r"(t.x));
    return r;
}
__device__ __forceinline__ uint32_t saddr(const void* p) {
    return (uint32_t)__cvta_generic_to_shared(p);
}
__device__ __forceinline__ void lds_v2(u64& a, u64& b, uint32_t addr) {
    asm volatile("ld.shared.v2.b64 {%0,%1},[%2];" : "=l"(a), "=l"(b) : "r"(addr));
}
__device__ __forceinline__ void ldg_v2(u64& a, u64& b, const void* p) {
    asm("ld.global.nc.v2.b64 {%0,%1},[%2];" : "=l"(a), "=l"(b) : "l"(p));
}
__device__ __forceinline__ void ldg_v2_c(u64& a, u64& b, const void* p) {
    asm volatile("ld.global.v2.b64 {%0,%1},[%2];" : "=l"(a), "=l"(b) : "l"(p));
}
__device__ __forceinline__ void stg_v2(void* p, u64 a, u64 b) {
    asm volatile("st.global.v2.b64 [%0],{%1,%2};" :: "l"(p), "l"(a), "l"(b));
}
__device__ __forceinline__ void ldg4(u64* k, const float2* p) {
    ldg_v2(k[0], k[1], p);
    ldg_v2(k[2], k[3], p + 2);
}
__device__ __forceinline__ void pref_l2(const void* p) {
    asm volatile("prefetch.global.L2 [%0];" :: "l"(p));
}

// ---- setup ----
__global__ void setup_kernel(const float* __restrict__ kW, const float* __restrict__ kF) {
    int i = blockIdx.x * blockDim.x + threadIdx.x;
    if (i < 2048) {
        float s, c;
        sincosf(kW[i], &s, &c);
        c *= 0.125f; s *= 0.125f;
        g_W4[i] = make_float4(c, c, s, -s);     // conj form
        sincosf(kF[i], &s, &c);
        c *= 0.125f; s *= 0.125f;
        g_F4[i] = make_float4(c, c, -s, s);     // mul form
    }
}

// =====================================================================
// R12-proven core: 8 rows x 2 cols, K=64, depth-2 register prefetch,
// L2 prefetch(+6), guard-peeled. TSTRIDE = table bytes per dd step.
// =====================================================================
#define C8X2_BODY(DD)                                                        \
    {                                                                        \
        const u64 ks0 = swap2(ka0), ks1 = swap2(ka1);                        \
        _Pragma("unroll")                                                    \
        for (int i = 0; i < 8; ++i) {                                        \
            u64 wxx, wyn;                                                    \
            lds_v2(wxx, wyn, taddr_ + (uint32_t)(DD) * tstep_ + i * 16);     \
            acc0[i] = ffma2(wyn, ks0, ffma2(wxx, ka0, acc0[i]));             \
            acc1[i] = ffma2(wyn, ks1, ffma2(wxx, ka1, acc1[i]));             \
        }                                                                    \
        ka0 = kb0; ka1 = kb1; kb0 = kn0; kb1 = kn1;                          \
    }

#define CORE8x2(PTR, STRIDE, TADDR, TSTRIDE)                                 \
    u64 acc0[8], acc1[8];                                                    \
    _Pragma("unroll")                                                        \
    for (int i = 0; i < 8; ++i) { acc0[i] = 0ull; acc1[i] = 0ull; }          \
    const uint32_t taddr_ = (TADDR);                                         \
    const uint32_t tstep_ = (TSTRIDE);                                       \
    u64 ka0, ka1, kb0, kb1;                                                  \
    ldg_v2(ka0, ka1, (PTR));                                                 \
    ldg_v2(kb0, kb1, (PTR) + (STRIDE));                                      \
    _Pragma("unroll")                                                        \
    for (int pd = 2; pd < 6; ++pd) pref_l2((PTR) + (size_t)pd * (STRIDE));   \
    _Pragma("unroll 2")                                                      \
    for (int dd = 0; dd < 56; ++dd) {                                        \
        u64 kn0, kn1;                                                        \
        ldg_v2(kn0, kn1, (PTR) + (size_t)(dd + 2) * (STRIDE));               \
        pref_l2((PTR) + (size_t)(dd + 6) * (STRIDE));                        \
        C8X2_BODY(dd)                                                        \
    }                                                                        \
    _Pragma("unroll 2")                                                      \
    for (int dd = 56; dd < 62; ++dd) {                                       \
        u64 kn0, kn1;                                                        \
        ldg_v2(kn0, kn1, (PTR) + (size_t)(dd + 2) * (STRIDE));               \
        C8X2_BODY(dd)                                                        \
    }                                                                        \
    _Pragma("unroll")                                                        \
    for (int dd = 62; dd < 64; ++dd) {                                       \
        u64 kn0 = 0ull, kn1 = 0ull;                                          \
        C8X2_BODY(dd)                                                        \
    }

// Half-table load (1024 entries = 16 rows x 64 dd), 128 threads, 8 each.
// Tab[dd*16 + r] = SRC[dd*32 + HBASE + r]
#define LOAD_HALF(SRC, HBASE)                                                \
    _Pragma("unroll")                                                        \
    for (int k = 0; k < 8; ++k) {                                            \
        int i = threadIdx.x + 128 * k;                                       \
        Tab[i] = SRC[(i >> 4) * 32 + (HBASE) + (i & 15)];                    \
    }                                                                        \
    __syncthreads();

// =====================================================================
// k1, grid 7168, 128 thr, stripe: bid%7==6 -> y2n (1024, inits Y);
// else oid = bid - bid/7:  [0,4096) sA halves, [4096,6144) y1 halves.
// =====================================================================
__global__ void __launch_bounds__(128, 6) k1_kernel(const float2* __restrict__ K,
                                                    const float2* __restrict__ H,
                                                    const float2* __restrict__ noise,
                                                    float2* __restrict__ Y) {
    __shared__ float4 Tab[2048];
    const int t = threadIdx.x;
    const unsigned bid = blockIdx.x;

    if (bid % 7u == 6u) {
        // ---------------- y2n (half x-range) ----------------
        const int blk = bid / 7u;                 // 0..1023
        const int b = blk >> 4, rh = blk & 15;
        const int r = rh >> 1, xh = rh & 1;
        // mini-table: Wn[n*4+j], 256 entries, 2 per thread
        Tab[t]       = g_W4[(t >> 2) * 32 + r * 4 + (t & 3)];
        Tab[t + 128] = g_W4[((t + 128) >> 2) * 32 + r * 4 + (t & 3)];
        __syncthreads();

        const int x0 = xh * 512 + t * 4;
        const uint32_t wn = saddr(Tab);
        const float2* np = noise + (size_t)(b * 8 + r) * 65536 + x0;

        u64 acc[4][4];
#pragma unroll
        for (int j = 0; j < 4; ++j)
#pragma unroll
            for (int q = 0; q < 4; ++q) acc[j][q] = 0ull;

#define Y2N_BODY(N)                                                          \
        {                                                                    \
            const u64 w0 = swap2(v[0]), w1 = swap2(v[1]),                    \
                      w2 = swap2(v[2]), w3 = swap2(v[3]);                    \
            _Pragma("unroll")                                                \
            for (int j = 0; j < 4; ++j) {                                    \
                u64 wxx, wyn;                                                \
                lds_v2(wxx, wyn, wn + (uint32_t)(((N) * 4 + j) << 4));       \
                acc[j][0] = ffma2(wyn, w0, ffma2(wxx, v[0], acc[j][0]));     \
                acc[j][1] = ffma2(wyn, w1, ffma2(wxx, v[1], acc[j][1]));     \
                acc[j][2] = ffma2(wyn, w2, ffma2(wxx, v[2], acc[j][2]));     \
                acc[j][3] = ffma2(wyn, w3, ffma2(wxx, v[3], acc[j][3]));     \
            }                                                                \
        }

#pragma unroll 4
        for (int n = 0; n < 56; ++n) {
            u64 v[4];
            ldg4(v, np + (size_t)n * 1024);
            pref_l2(np + (size_t)(n + 8) * 1024);
            Y2N_BODY(n)
        }
#pragma unroll 4
        for (int n = 56; n < 64; ++n) {
            u64 v[4];
            ldg4(v, np + (size_t)n * 1024);
            Y2N_BODY(n)
        }

        const int a = x0 >> 5, s = x0 & 31;
#pragma unroll
        for (int j = 0; j < 4; ++j) {
            float2* yp = Y + (size_t)(b * 1024 + a * 32 + r * 4 + j) * 32 + s;
            stg_v2(yp,     acc[j][0], acc[j][1]);     // WRITE (init)
            stg_v2(yp + 2, acc[j][2], acc[j][3]);
        }
        return;
    }

    const int oid = (int)(bid - bid / 7u);        // 0..6143
    const int gp = t & 63, rg = t >> 6;           // rg in {0,1}

    if (oid < 4096) {
        // ---------------- sA (16 bp half) ----------------
        const int c = oid >> 6, sub = oid & 63;
        const int gt = sub >> 1, bph = sub & 1;
        LOAD_HALF(g_W4, bph * 16)
        const int g = gt * 128 + gp * 2;
        const float2* Kp = K + (size_t)(c * 64) * G2 + g;
        const uint32_t taddr = saddr(Tab) + (uint32_t)(rg * 8) * 16;

        CORE8x2(Kp, G2, taddr, 256)

        const int bp0 = bph * 16 + rg * 8;
#pragma unroll
        for (int i = 0; i < 8; ++i) {
            float2* Sp = g_S + (size_t)(c * 32 + bp0 + i) * G2 + g;
            stg_v2(Sp, acc0[i], acc1[i]);
        }
    } else {
        // ---------------- y1 (16 m half) ----------------
        const int yid = oid - 4096;               // 0..2047
        const int b = yid >> 5, sub = yid & 31;
        const int cst = sub >> 1, mh = sub & 1;
        LOAD_HALF(g_W4, mh * 16)
        const int cs = cst * 128 + gp * 2;
        const float2* Hp = H + (size_t)b * 131072 + cs;    // + d*2048
        const uint32_t taddr = saddr(Tab) + (uint32_t)(rg * 8) * 16;

        CORE8x2(Hp, 2048, taddr, 256)

        const int m0 = mh * 16 + rg * 8;
#pragma unroll
        for (int i = 0; i < 8; ++i) {
            float2* Gp = g_G1 + (size_t)(b * 32 + m0 + i) * 2048 + cs;
            stg_v2(Gp, acc0[i], acc1[i]);
        }
    }
}

// =====================================================================
// k2, grid 3072, 128 thr, stripe: bid%3==2 -> y2s (1024, 2 bm, RMW);
// else pid = bid - bid/3 in [0,2048) -> phiB (16 a half).
// =====================================================================
__global__ void __launch_bounds__(128, 6) k2_kernel(float2* __restrict__ Phi,
                                                    float2* __restrict__ Y) {
    __shared__ float4 Tab[2048];
    const int t = threadIdx.x;
    const unsigned bid = blockIdx.x;

    if (bid % 3u == 2u) {
        // ---------------- y2s (2 bm, RMW, full F table) ----------------
#pragma unroll
        for (int k = 0; k < 16; ++k) Tab[t + 128 * k] = g_F4[t + 128 * k];
        __syncthreads();

        const int sid = bid / 3u;                 // 0..1023
        const int bm = sid * 2 + (t >> 6);
        const int b = bm >> 5, m = bm & 31;
        const int tt = t & 63;
        const int sp = tt & 15, ag = tt >> 4;     // ag in {0..3}
        const int s = sp * 2;

        const float2* Gp = g_G1 + (size_t)bm * 2048 + s;   // + c*32
        const uint32_t faddr = saddr(Tab) + (uint32_t)(ag * 8) * 16;

        CORE8x2(Gp, 32, faddr, 512)

#pragma unroll
        for (int i = 0; i < 8; ++i) {
            float2* yp = Y + (size_t)(b * 1024 + (ag * 8 + i) * 32 + m) * 32 + s;
            u64 y0, y1;
            ldg_v2_c(y0, y1, yp);
            stg_v2(yp, fadd2(y0, acc0[i]), fadd2(y1, acc1[i]));
        }
    } else {
        // ---------------- phiB (16 a half) ----------------
        const int pid = (int)(bid - bid / 3u);    // 0..2047
        const int bp = pid >> 6, sub = pid & 63;
        const int gt = sub >> 1, ah = sub & 1;
#pragma unroll
        for (int k = 0; k < 8; ++k) {
            int i = t + 128 * k;
            Tab[i] = g_F4[(i >> 4) * 32 + ah * 16 + (i & 15)];
        }
        __syncthreads();

        const int gp = t & 63, rg = t >> 6;
        const int g = gt * 128 + gp * 2;
        const float2* Sp = g_S + (size_t)bp * G2 + g;      // + c*32*G2
        const uint32_t faddr = saddr(Tab) + (uint32_t)(rg * 8) * 16;

        CORE8x2(Sp, (size_t)32 * G2, faddr, 256)

        const int a0 = ah * 16 + rg * 8;
#pragma unroll
        for (int i = 0; i < 8; ++i) {
            float2* Pp = Phi + (size_t)((a0 + i) * 32 + bp) * G2 + g;
            stg_v2(Pp, acc0[i], acc1[i]);
        }
    }
}

extern "C" void kernel_launch(void* const* d_in, const int* in_sizes, int n_in,
                              void* d_out, int out_size) {
    const float2* H     = (const float2*)d_in[0];  // (64,64,64,32,2) f32
    const float2* noise = (const float2*)d_in[1];  // (64,8,64,1024,2) f32
    const float*  kW    = (const float*)d_in[2];   // (64,32)
    const float*  kF    = (const float*)d_in[3];   // (64,32)
    const float2* K     = (const float2*)d_in[4];  // (4096,4096,2)

    float2* Phi = (float2*)d_out;                   // 1024*4096 complex
    float2* Y   = Phi + (size_t)1024 * 4096;        // 64*1024*32 complex

    setup_kernel<<<8, 256>>>(kW, kF);
    k1_kernel<<<7168, 128>>>(K, H, noise, Y);
    k2_kernel<<<3072, 128>>>(Phi, Y);
}

// round 15
// speedup vs baseline: 1.0924x; 1.0409x over previous
#include <cuda_runtime.h>
#include <cstdint>

// Dims: Nt=64, Nr=64, Mt=32, Mr=32, G^2=4096, num_sc=32, B=64, R=8, N_r_RF=4
#define G2 4096
typedef unsigned long long u64;

// ---- device globals (no allocation allowed) ----
__device__ float4 g_W4[2048];   // [d*32+m] = (w.x,w.x,w.y,-w.y)  conj form
__device__ float4 g_F4[2048];   // [c*32+a] = (f.x,f.x,-f.y,f.y)  mul form
__device__ float2 g_S [(size_t)2048 * 4096];        // S[c*32+bp][g], 64 MB
__device__ float2 g_G1[(size_t)2048 * 2048];        // G1[b*32+m][c*32+s], 32 MB

// ---- f32x2 packed helpers ----
__device__ __forceinline__ u64 ffma2(u64 a, u64 b, u64 c) {
    u64 d; asm("fma.rn.f32x2 %0,%1,%2,%3;" : "=l"(d) : "l"(a), "l"(b), "l"(c)); return d;
}
__device__ __forceinline__ u64 fadd2(u64 a, u64 b) {
    u64 d; asm("add.rn.f32x2 %0,%1,%2;" : "=l"(d) : "l"(a), "l"(b)); return d;
}
__device__ __forceinline__ u64 swap2(u64 v) {
    uint2 t; asm("mov.b64 {%0,%1},%2;" : "=r"(t.x), "=r"(t.y) : "l"(v));
    u64 r;  asm("mov.b64 %0,{%1,%2};" : "=l"(r) : "r"(t.y), "r"(t.x));
    return r;
}
__device__ __forceinline__ uint32_t saddr(const void* p) {
    return (uint32_t)__cvta_generic_to_shared(p);
}
__device__ __forceinline__ void lds_v2(u64& a, u64& b, uint32_t addr) {
    asm volatile("ld.shared.v2.b64 {%0,%1},[%2];" : "=l"(a), "=l"(b) : "r"(addr));
}
__device__ __forceinline__ void ldg_v2(u64& a, u64& b, const void* p) {
    asm("ld.global.nc.v2.b64 {%0,%1},[%2];" : "=l"(a), "=l"(b) : "l"(p));
}
__device__ __forceinline__ void ldg_v2_c(u64& a, u64& b, const void* p) {
    asm volatile("ld.global.v2.b64 {%0,%1},[%2];" : "=l"(a), "=l"(b) : "l"(p));
}
__device__ __forceinline__ void stg_v2(void* p, u64 a, u64 b) {
    asm volatile("st.global.v2.b64 [%0],{%1,%2};" :: "l"(p), "l"(a), "l"(b));
}
__device__ __forceinline__ void ldg4(u64* k, const float2* p) {
    ldg_v2(k[0], k[1], p);
    ldg_v2(k[2], k[3], p + 2);
}
__device__ __forceinline__ void pref_l2(const void* p) {
    asm volatile("prefetch.global.L2 [%0];" :: "l"(p));
}

// ---- setup ----
__global__ void setup_kernel(const float* __restrict__ kW, const float* __restrict__ kF) {
    int i = blockIdx.x * blockDim.x + threadIdx.x;
    if (i < 2048) {
        float s, c;
        sincosf(kW[i], &s, &c);
        c *= 0.125f; s *= 0.125f;
        g_W4[i] = make_float4(c, c, s, -s);     // conj form
        sincosf(kF[i], &s, &c);
        c *= 0.125f; s *= 0.125f;
        g_F4[i] = make_float4(c, c, -s, s);     // mul form
    }
}

// =====================================================================
// Core: 8 rows x 2 cols, K=64, DEPTH-3 register pipeline (covers
// far-die L2 262cyc), L2 prefetch(+6), guard-peeled.
// Per dd (hot): 8 LDS.v2(bcast) + 1 LDG.v2 + 1 pref + 2 swaps + 32 FFMA2.
// =====================================================================
#define C8X2_BODY(DD)                                                        \
    {                                                                        \
        const u64 ks0 = swap2(ka0), ks1 = swap2(ka1);                        \
        _Pragma("unroll")                                                    \
        for (int i = 0; i < 8; ++i) {                                        \
            u64 wxx, wyn;                                                    \
            lds_v2(wxx, wyn, taddr_ + (uint32_t)(DD) * tstep_ + i * 16);     \
            acc0[i] = ffma2(wyn, ks0, ffma2(wxx, ka0, acc0[i]));             \
            acc1[i] = ffma2(wyn, ks1, ffma2(wxx, ka1, acc1[i]));             \
        }                                                                    \
        ka0 = kb0; ka1 = kb1; kb0 = kc0; kb1 = kc1; kc0 = kn0; kc1 = kn1;    \
    }

#define CORE8x2(PTR, STRIDE, TADDR, TSTRIDE)                                 \
    u64 acc0[8], acc1[8];                                                    \
    _Pragma("unroll")                                                        \
    for (int i = 0; i < 8; ++i) { acc0[i] = 0ull; acc1[i] = 0ull; }          \
    const uint32_t taddr_ = (TADDR);                                         \
    const uint32_t tstep_ = (TSTRIDE);                                       \
    u64 ka0, ka1, kb0, kb1, kc0, kc1;                                        \
    ldg_v2(ka0, ka1, (PTR));                                                 \
    ldg_v2(kb0, kb1, (PTR) + (STRIDE));                                      \
    ldg_v2(kc0, kc1, (PTR) + 2 * (STRIDE));                                  \
    _Pragma("unroll")                                                        \
    for (int pd = 3; pd < 9; ++pd) pref_l2((PTR) + (size_t)pd * (STRIDE));   \
    _Pragma("unroll 3")                                                      \
    for (int dd = 0; dd < 54; ++dd) {                                        \
        u64 kn0, kn1;                                                        \
        ldg_v2(kn0, kn1, (PTR) + (size_t)(dd + 3) * (STRIDE));               \
        pref_l2((PTR) + (size_t)(dd + 9) * (STRIDE));                        \
        C8X2_BODY(dd)                                                        \
    }                                                                        \
    _Pragma("unroll")                                                        \
    for (int dd = 54; dd < 61; ++dd) {                                       \
        u64 kn0, kn1;                                                        \
        ldg_v2(kn0, kn1, (PTR) + (size_t)(dd + 3) * (STRIDE));               \
        C8X2_BODY(dd)                                                        \
    }                                                                        \
    _Pragma("unroll")                                                        \
    for (int dd = 61; dd < 64; ++dd) {                                       \
        u64 kn0 = 0ull, kn1 = 0ull;                                          \
        C8X2_BODY(dd)                                                        \
    }

// Half-table load (1024 entries = 16 rows x 64 dd), 128 threads, 8 each.
// Tab[dd*16 + r] = SRC[dd*32 + HBASE + r]
#define LOAD_HALF(SRC, HBASE)                                                \
    _Pragma("unroll")                                                        \
    for (int k = 0; k < 8; ++k) {                                            \
        int i = threadIdx.x + 128 * k;                                       \
        Tab[i] = SRC[(i >> 4) * 32 + (HBASE) + (i & 15)];                    \
    }                                                                        \
    __syncthreads();

// =====================================================================
// k1, grid 7168, 128 thr, stripe: bid%7==6 -> y2n (1024, inits Y);
// else oid = bid - bid/7:  [0,4096) sA halves, [4096,6144) y1 halves.
// =====================================================================
__global__ void __launch_bounds__(128, 6) k1_kernel(const float2* __restrict__ K,
                                                    const float2* __restrict__ H,
                                                    const float2* __restrict__ noise,
                                                    float2* __restrict__ Y) {
    __shared__ float4 Tab[2048];
    const int t = threadIdx.x;
    const unsigned bid = blockIdx.x;

    if (bid % 7u == 6u) {
        // ---------------- y2n (half x-range) ----------------
        const int blk = bid / 7u;                 // 0..1023
        const int b = blk >> 4, rh = blk & 15;
        const int r = rh >> 1, xh = rh & 1;
        // mini-table: Wn[n*4+j], 256 entries, 2 per thread
        Tab[t]       = g_W4[(t >> 2) * 32 + r * 4 + (t & 3)];
        Tab[t + 128] = g_W4[((t + 128) >> 2) * 32 + r * 4 + (t & 3)];
        __syncthreads();

        const int x0 = xh * 512 + t * 4;
        const uint32_t wn = saddr(Tab);
        const float2* np = noise + (size_t)(b * 8 + r) * 65536 + x0;

        u64 acc[4][4];
#pragma unroll
        for (int j = 0; j < 4; ++j)
#pragma unroll
            for (int q = 0; q < 4; ++q) acc[j][q] = 0ull;

#define Y2N_BODY(N)                                                          \
        {                                                                    \
            const u64 w0 = swap2(v[0]), w1 = swap2(v[1]),                    \
                      w2 = swap2(v[2]), w3 = swap2(v[3]);                    \
            _Pragma("unroll")                                                \
            for (int j = 0; j < 4; ++j) {                                    \
                u64 wxx, wyn;                                                \
                lds_v2(wxx, wyn, wn + (uint32_t)(((N) * 4 + j) << 4));       \
                acc[j][0] = ffma2(wyn, w0, ffma2(wxx, v[0], acc[j][0]));     \
                acc[j][1] = ffma2(wyn, w1, ffma2(wxx, v[1], acc[j][1]));     \
                acc[j][2] = ffma2(wyn, w2, ffma2(wxx, v[2], acc[j][2]));     \
                acc[j][3] = ffma2(wyn, w3, ffma2(wxx, v[3], acc[j][3]));     \
            }                                                                \
        }

#pragma unroll 4
        for (int n = 0; n < 56; ++n) {
            u64 v[4];
            ldg4(v, np + (size_t)n * 1024);
            pref_l2(np + (size_t)(n + 8) * 1024);
            Y2N_BODY(n)
        }
#pragma unroll 4
        for (int n = 56; n < 64; ++n) {
            u64 v[4];
            ldg4(v, np + (size_t)n * 1024);
            Y2N_BODY(n)
        }

        const int a = x0 >> 5, s = x0 & 31;
#pragma unroll
        for (int j = 0; j < 4; ++j) {
            float2* yp = Y + (size_t)(b * 1024 + a * 32 + r * 4 + j) * 32 + s;
            stg_v2(yp,     acc[j][0], acc[j][1]);     // WRITE (init)
            stg_v2(yp + 2, acc[j][2], acc[j][3]);
        }
        return;
    }

    const int oid = (int)(bid - bid / 7u);        // 0..6143
    const int gp = t & 63, rg = t >> 6;           // rg in {0,1}

    if (oid < 4096) {
        // ---------------- sA (16 bp half) ----------------
        const int c = oid >> 6, sub = oid & 63;
        const int gt = sub >> 1, bph = sub & 1;
        LOAD_HALF(g_W4, bph * 16)
        const int g = gt * 128 + gp * 2;
        const float2* Kp = K + (size_t)(c * 64) * G2 + g;
        const uint32_t taddr = saddr(Tab) + (uint32_t)(rg * 8) * 16;

        CORE8x2(Kp, G2, taddr, 256)

        const int bp0 = bph * 16 + rg * 8;
#pragma unroll
        for (int i = 0; i < 8; ++i) {
            float2* Sp = g_S + (size_t)(c * 32 + bp0 + i) * G2 + g;
            stg_v2(Sp, acc0[i], acc1[i]);
        }
    } else {
        // ---------------- y1 (16 m half) ----------------
        const int yid = oid - 4096;               // 0..2047
        const int b = yid >> 5, sub = yid & 31;
        const int cst = sub >> 1, mh = sub & 1;
        LOAD_HALF(g_W4, mh * 16)
        const int cs = cst * 128 + gp * 2;
        const float2* Hp = H + (size_t)b * 131072 + cs;    // + d*2048
        const uint32_t taddr = saddr(Tab) + (uint32_t)(rg * 8) * 16;

        CORE8x2(Hp, 2048, taddr, 256)

        const int m0 = mh * 16 + rg * 8;
#pragma unroll
        for (int i = 0; i < 8; ++i) {
            float2* Gp = g_G1 + (size_t)(b * 32 + m0 + i) * 2048 + cs;
            stg_v2(Gp, acc0[i], acc1[i]);
        }
    }
}

// =====================================================================
// k2, grid 3072, 128 thr, stripe: bid%3==2 -> y2s (1024, 2 bm, RMW);
// else pid = bid - bid/3 in [0,2048) -> phiB (16 a half).
// =====================================================================
__global__ void __launch_bounds__(128, 6) k2_kernel(float2* __restrict__ Phi,
                                                    float2* __restrict__ Y) {
    __shared__ float4 Tab[2048];
    const int t = threadIdx.x;
    const unsigned bid = blockIdx.x;

    if (bid % 3u == 2u) {
        // ---------------- y2s (2 bm, RMW, full F table) ----------------
#pragma unroll
        for (int k = 0; k < 16; ++k) Tab[t + 128 * k] = g_F4[t + 128 * k];
        __syncthreads();

        const int sid = bid / 3u;                 // 0..1023
        const int bm = sid * 2 + (t >> 6);
        const int b = bm >> 5, m = bm & 31;
        const int tt = t & 63;
        const int sp = tt & 15, ag = tt >> 4;     // ag in {0..3}
        const int s = sp * 2;

        const float2* Gp = g_G1 + (size_t)bm * 2048 + s;   // + c*32
        const uint32_t faddr = saddr(Tab) + (uint32_t)(ag * 8) * 16;

        CORE8x2(Gp, 32, faddr, 512)

#pragma unroll
        for (int i = 0; i < 8; ++i) {
            float2* yp = Y + (size_t)(b * 1024 + (ag * 8 + i) * 32 + m) * 32 + s;
            u64 y0, y1;
            ldg_v2_c(y0, y1, yp);
            stg_v2(yp, fadd2(y0, acc0[i]), fadd2(y1, acc1[i]));
        }
    } else {
        // ---------------- phiB (16 a half) ----------------
        const int pid = (int)(bid - bid / 3u);    // 0..2047
        const int bp = pid >> 6, sub = pid & 63;
        const int gt = sub >> 1, ah = sub & 1;
#pragma unroll
        for (int k = 0; k < 8; ++k) {
            int i = t + 128 * k;
            Tab[i] = g_F4[(i >> 4) * 32 + ah * 16 + (i & 15)];
        }
        __syncthreads();

        const int gp = t & 63, rg = t >> 6;
        const int g = gt * 128 + gp * 2;
        const float2* Sp = g_S + (size_t)bp * G2 + g;      // + c*32*G2
        const uint32_t faddr = saddr(Tab) + (uint32_t)(rg * 8) * 16;

        CORE8x2(Sp, (size_t)32 * G2, faddr, 256)

        const int a0 = ah * 16 + rg * 8;
#pragma unroll
        for (int i = 0; i < 8; ++i) {
            float2* Pp = Phi + (size_t)((a0 + i) * 32 + bp) * G2 + g;
            stg_v2(Pp, acc0[i], acc1[i]);
        }
    }
}

extern "C" void kernel_launch(void* const* d_in, const int* in_sizes, int n_in,
                              void* d_out, int out_size) {
    const float2* H     = (const float2*)d_in[0];  // (64,64,64,32,2) f32
    const float2* noise = (const float2*)d_in[1];  // (64,8,64,1024,2) f32
    const float*  kW    = (const float*)d_in[2];   // (64,32)
    const float*  kF    = (const float*)d_in[3];   // (64,32)
    const float2* K     = (const float2*)d_in[4];  // (4096,4096,2)

    float2* Phi = (float2*)d_out;                   // 1024*4096 complex
    float2* Y   = Phi + (size_t)1024 * 4096;        // 64*1024*32 complex

    setup_kernel<<<8, 256>>>(kW, kF);
    k1_kernel<<<7168, 128>>>(K, H, noise, Y);
    k2_kernel<<<3072, 128>>>(Phi, Y);
}